// round 1
// baseline (speedup 1.0000x reference)
#include <cuda_runtime.h>
#include <math.h>

#define BN   20800
#define T_   24
#define F_   64
#define H_   128
#define H2_  256
#define H3_  384
#define TR   48          // rows per CTA
#define TRP  49          // padded smem row stride
#define RPT  6           // rows per thread
#define NCTA ((BN + TR - 1) / TR)   // 434

// scratch: layer-0 output sequence [BN][T][H]
__device__ float g_seq1[(size_t)BN * T_ * H_];
// pre-transposed weights: [k][c]
__device__ float g_wihT[F_ * H3_];
__device__ float g_whhT[H_ * H3_];
__device__ float g_gwT[H2_ * H2_];
__device__ float g_owT[H2_ * H_];

__global__ void transpose_weights(const float* __restrict__ w_ih,
                                  const float* __restrict__ w_hh,
                                  const float* __restrict__ gate_w,
                                  const float* __restrict__ out_w)
{
    int idx = blockIdx.x * blockDim.x + threadIdx.x;
    if (idx < H3_ * F_)  { int c = idx / F_,  k = idx % F_;  g_wihT[k * H3_ + c] = w_ih[idx]; }
    if (idx < H3_ * H_)  { int c = idx / H_,  k = idx % H_;  g_whhT[k * H3_ + c] = w_hh[idx]; }
    if (idx < H2_ * H2_) { int c = idx / H2_, k = idx % H2_; g_gwT[k * H2_ + c] = gate_w[idx]; }
    if (idx < H_ * H2_)  { int c = idx / H2_, k = idx % H2_; g_owT[k * H_ + c] = out_w[idx]; }
}

__device__ __forceinline__ float sigmoidf_(float v) {
    return 1.0f / (1.0f + __expf(-v));
}

// acc[i][j] += A[k][row0+i] * Wt[k][col j], K steps.
// A: smem [K][TRP] (broadcast reads within a warp). Wt: gmem, already offset to this
// thread's 4 columns; lanes of a warp cover 128 contiguous floats -> coalesced LDG.128.
template<int K>
__device__ __forceinline__ void mm_acc(float acc[RPT][4],
                                       const float* __restrict__ A,
                                       const float* __restrict__ Wt,
                                       int ldw, int row0)
{
    #pragma unroll 8
    for (int k = 0; k < K; ++k) {
        float4 w = __ldg(reinterpret_cast<const float4*>(Wt + (size_t)k * ldw));
        const float* ap = A + k * TRP + row0;
        float a[RPT];
        #pragma unroll
        for (int i = 0; i < RPT; ++i) a[i] = ap[i];
        #pragma unroll
        for (int i = 0; i < RPT; ++i) {
            acc[i][0] = fmaf(a[i], w.x, acc[i][0]);
            acc[i][1] = fmaf(a[i], w.y, acc[i][1]);
            acc[i][2] = fmaf(a[i], w.z, acc[i][2]);
            acc[i][3] = fmaf(a[i], w.w, acc[i][3]);
        }
    }
}

#define ZERO_ACC(A)                                   \
    _Pragma("unroll")                                 \
    for (int i = 0; i < RPT; ++i)                     \
        _Pragma("unroll")                             \
        for (int j = 0; j < 4; ++j) (A)[i][j] = 0.0f;

// ---------------- Layer 0: torch GRUCell over T steps ----------------
__global__ __launch_bounds__(256, 1)
void gru_layer0(const float* __restrict__ x,
                const float* __restrict__ b_ih,
                const float* __restrict__ b_hh)
{
    __shared__ float x_s[F_ * TRP];   // x_t transposed [f][r]
    __shared__ float h_s[H_ * TRP];   // h transposed [k][r]

    const int tid  = threadIdx.x;
    const int rg   = tid >> 5, cg = tid & 31;
    const int row0 = rg * RPT;
    const int c4   = cg * 4;
    const int bn0  = blockIdx.x * TR;

    for (int i = tid; i < H_ * TRP; i += 256) h_s[i] = 0.0f;

    float br[4], bz[4], bi_n[4], bh_n[4];
    #pragma unroll
    for (int j = 0; j < 4; ++j) {
        br[j]   = b_ih[c4 + j]        + b_hh[c4 + j];
        bz[j]   = b_ih[H_ + c4 + j]   + b_hh[H_ + c4 + j];
        bi_n[j] = b_ih[2 * H_ + c4 + j];
        bh_n[j] = b_hh[2 * H_ + c4 + j];
    }

    for (int t = 0; t < T_; ++t) {
        // load x_t tile (48 rows x 64 f), transposed into smem
        #pragma unroll
        for (int u = 0; u < 3; ++u) {
            int idx = tid + u * 256;       // 0..767 float4 slots
            int r = idx >> 4;
            int f = (idx & 15) * 4;
            float4 v = make_float4(0.f, 0.f, 0.f, 0.f);
            int bn = bn0 + r;
            if (bn < BN)
                v = *reinterpret_cast<const float4*>(x + ((size_t)bn * T_ + t) * F_ + f);
            x_s[(f + 0) * TRP + r] = v.x;
            x_s[(f + 1) * TRP + r] = v.y;
            x_s[(f + 2) * TRP + r] = v.z;
            x_s[(f + 3) * TRP + r] = v.w;
        }
        __syncthreads();   // x_s ready; h_s writes from prev step visible

        float accA[RPT][4], accB[RPT][4];

        // r gate (cols 0..127): gi + gh
        ZERO_ACC(accA); ZERO_ACC(accB);
        mm_acc<F_>(accA, x_s, g_wihT + c4, H3_, row0);
        mm_acc<H_>(accB, h_s, g_whhT + c4, H3_, row0);
        float rr[RPT][4];
        #pragma unroll
        for (int i = 0; i < RPT; ++i)
            #pragma unroll
            for (int j = 0; j < 4; ++j)
                rr[i][j] = sigmoidf_(accA[i][j] + accB[i][j] + br[j]);

        // z gate (cols 128..255)
        ZERO_ACC(accA); ZERO_ACC(accB);
        mm_acc<F_>(accA, x_s, g_wihT + H_ + c4, H3_, row0);
        mm_acc<H_>(accB, h_s, g_whhT + H_ + c4, H3_, row0);
        float zz[RPT][4];
        #pragma unroll
        for (int i = 0; i < RPT; ++i)
            #pragma unroll
            for (int j = 0; j < 4; ++j)
                zz[i][j] = sigmoidf_(accA[i][j] + accB[i][j] + bz[j]);

        // n gate (cols 256..383): keep gi and gh separate
        ZERO_ACC(accA); ZERO_ACC(accB);
        mm_acc<F_>(accA, x_s, g_wihT + 2 * H_ + c4, H3_, row0);
        mm_acc<H_>(accB, h_s, g_whhT + 2 * H_ + c4, H3_, row0);

        float hn[RPT][4];
        #pragma unroll
        for (int i = 0; i < RPT; ++i)
            #pragma unroll
            for (int j = 0; j < 4; ++j) {
                float hold = h_s[(c4 + j) * TRP + row0 + i];
                float n = tanhf(accA[i][j] + bi_n[j] + rr[i][j] * (accB[i][j] + bh_n[j]));
                hn[i][j] = (1.f - zz[i][j]) * n + zz[i][j] * hold;
            }
        __syncthreads();   // all reads of h_s / x_s done

        #pragma unroll
        for (int i = 0; i < RPT; ++i) {
            #pragma unroll
            for (int j = 0; j < 4; ++j)
                h_s[(c4 + j) * TRP + row0 + i] = hn[i][j];
            int bn = bn0 + row0 + i;
            if (bn < BN)
                *reinterpret_cast<float4*>(g_seq1 + ((size_t)bn * T_ + t) * H_ + c4)
                    = make_float4(hn[i][0], hn[i][1], hn[i][2], hn[i][3]);
        }
        // next iteration's post-load __syncthreads orders these writes vs. reads
    }
}

// ---------------- Layer 1: custom GRUCell over T steps ----------------
__global__ __launch_bounds__(256, 1)
void gru_layer1(const float* __restrict__ gate_b,
                const float* __restrict__ out_b,
                float* __restrict__ out)
{
    __shared__ float x_s[H_ * TRP];
    __shared__ float h_s[H_ * TRP];
    __shared__ float rh_s[H_ * TRP];

    const int tid  = threadIdx.x;
    const int rg   = tid >> 5, cg = tid & 31;
    const int row0 = rg * RPT;
    const int c4   = cg * 4;
    const int bn0  = blockIdx.x * TR;

    for (int i = tid; i < H_ * TRP; i += 256) h_s[i] = 0.0f;

    float bgr[4], bgz[4], bo[4];
    #pragma unroll
    for (int j = 0; j < 4; ++j) {
        bgr[j] = gate_b[c4 + j];
        bgz[j] = gate_b[H_ + c4 + j];
        bo[j]  = out_b[c4 + j];
    }

    for (int t = 0; t < T_; ++t) {
        // load x_t = seq1[:, t, :] tile (48 x 128), transposed
        #pragma unroll
        for (int u = 0; u < 6; ++u) {
            int idx = tid + u * 256;    // 0..1535 float4 slots
            int r = idx >> 5;
            int f = (idx & 31) * 4;
            float4 v = make_float4(0.f, 0.f, 0.f, 0.f);
            int bn = bn0 + r;
            if (bn < BN)
                v = *reinterpret_cast<const float4*>(g_seq1 + ((size_t)bn * T_ + t) * H_ + f);
            x_s[(f + 0) * TRP + r] = v.x;
            x_s[(f + 1) * TRP + r] = v.y;
            x_s[(f + 2) * TRP + r] = v.z;
            x_s[(f + 3) * TRP + r] = v.w;
        }
        __syncthreads();

        float acc[RPT][4];

        // r gate (cols 0..127 of gates), K = 256 split as x-part + h-part
        ZERO_ACC(acc);
        mm_acc<H_>(acc, x_s, g_gwT + c4, H2_, row0);
        mm_acc<H_>(acc, h_s, g_gwT + (size_t)H_ * H2_ + c4, H2_, row0);
        float rr[RPT][4];
        #pragma unroll
        for (int i = 0; i < RPT; ++i)
            #pragma unroll
            for (int j = 0; j < 4; ++j)
                rr[i][j] = sigmoidf_(acc[i][j] + bgr[j]);

        // z gate (cols 128..255)
        ZERO_ACC(acc);
        mm_acc<H_>(acc, x_s, g_gwT + H_ + c4, H2_, row0);
        mm_acc<H_>(acc, h_s, g_gwT + (size_t)H_ * H2_ + H_ + c4, H2_, row0);
        float zz[RPT][4];
        #pragma unroll
        for (int i = 0; i < RPT; ++i)
            #pragma unroll
            for (int j = 0; j < 4; ++j)
                zz[i][j] = sigmoidf_(acc[i][j] + bgz[j]);

        // r * h into smem (thread's r-cols == its h-feature cols)
        float hold[RPT][4];
        #pragma unroll
        for (int i = 0; i < RPT; ++i)
            #pragma unroll
            for (int j = 0; j < 4; ++j) {
                hold[i][j] = h_s[(c4 + j) * TRP + row0 + i];
                rh_s[(c4 + j) * TRP + row0 + i] = rr[i][j] * hold[i][j];
            }
        __syncthreads();   // rh_s ready; all h_s reads done

        // candidate: [x | r*h] @ out_w^T  (cols 0..127)
        ZERO_ACC(acc);
        mm_acc<H_>(acc, x_s,  g_owT + c4, H_, row0);
        mm_acc<H_>(acc, rh_s, g_owT + (size_t)H_ * H_ + c4, H_, row0);

        float hn[RPT][4];
        #pragma unroll
        for (int i = 0; i < RPT; ++i)
            #pragma unroll
            for (int j = 0; j < 4; ++j) {
                float cand = tanhf(acc[i][j] + bo[j]);
                hn[i][j] = zz[i][j] * hold[i][j] + (1.f - zz[i][j]) * cand;
            }
        __syncthreads();   // all x_s / rh_s reads done before overwrites

        #pragma unroll
        for (int i = 0; i < RPT; ++i) {
            #pragma unroll
            for (int j = 0; j < 4; ++j)
                h_s[(c4 + j) * TRP + row0 + i] = hn[i][j];
            int bn = bn0 + row0 + i;
            if (bn < BN)
                *reinterpret_cast<float4*>(out + ((size_t)bn * T_ + t) * H_ + c4)
                    = make_float4(hn[i][0], hn[i][1], hn[i][2], hn[i][3]);
        }
    }
}

extern "C" void kernel_launch(void* const* d_in, const int* in_sizes, int n_in,
                              void* d_out, int out_size)
{
    const float* x      = (const float*)d_in[0];
    const float* w_ih   = (const float*)d_in[1];
    const float* w_hh   = (const float*)d_in[2];
    const float* b_ih   = (const float*)d_in[3];
    const float* b_hh   = (const float*)d_in[4];
    const float* gate_w = (const float*)d_in[5];
    const float* gate_b = (const float*)d_in[6];
    const float* out_w  = (const float*)d_in[7];
    const float* out_b  = (const float*)d_in[8];
    float* out = (float*)d_out;

    transpose_weights<<<(H2_ * H2_ + 255) / 256, 256>>>(w_ih, w_hh, gate_w, out_w);
    gru_layer0<<<NCTA, 256>>>(x, b_ih, b_hh);
    gru_layer1<<<NCTA, 256>>>(gate_b, out_b, out);
}